// round 13
// baseline (speedup 1.0000x reference)
#include <cuda_runtime.h>
#include <math.h>
#include <stdint.h>

// Problem constants
#define NTH   512
#define PAD   65
#define NV    16
#define ND    64
#define NH    256
#define NC    128
#define NTOK  8192
#define TT    64     // wg token tile
#define GT    128    // xt token tile
#define GTOK  64     // gemm token tile
#define BK    16     // gemm k-chunk
#define NS    4      // pipeline stages
#define SP    132    // xt smem pad

typedef unsigned long long u64;

// Scratch (device globals: allocation-free rule)
__device__ float g_ctxp[32 * NH];
__device__ float g_xT[NV * ND * NTOK];        // x transposed [v][d][n] == flat^T [k][n]
__device__ float g_h1[NV * NH * NTOK];        // elu(fc1) [v][c][n]
__device__ float g_res[NV * NH * NTOK];       // skip residual [v][c][n]
__device__ float g_h2[NV * NH * NTOK];        // fc2 out [v][c][n]
__device__ float g_a[NV * NH * NTOK];         // glu a-half [v][c][n]
__device__ float g_hv[NTOK * NV * NH];        // raw hv (pre-LN) [n][v][c]
__device__ float g_wh1[NH * NTOK];            // wg h1 (post elu+ctx) [c][n]
__device__ float g_wres[NTOK * NV];           // wg skip residual [n][16]

__device__ __forceinline__ float elu_f(float x)  { return x > 0.f ? x : (__expf(x) - 1.f); }
__device__ __forceinline__ float sigm_f(float x) { return 1.f / (1.f + __expf(-x)); }
__device__ __forceinline__ float idf(float x)    { return x; }

// ---- packed fp32x2 helpers ----
__device__ __forceinline__ u64 pk2(float a, float b) {
    u64 r; asm("mov.b64 %0, {%1, %2};" : "=l"(r) : "f"(a), "f"(b)); return r;
}
__device__ __forceinline__ void fm2(u64& d, u64 a, u64 b) {
    asm("fma.rn.f32x2 %0, %1, %2, %0;" : "+l"(d) : "l"(a), "l"(b));
}
__device__ __forceinline__ float2 up2(u64 v) {
    float2 f; asm("mov.b64 {%0, %1}, %2;" : "=f"(f.x), "=f"(f.y) : "l"(v)); return f;
}

// ---- cp.async helpers ----
__device__ __forceinline__ void cpa16(unsigned int s, const void* g) {
    asm volatile("cp.async.cg.shared.global [%0], [%1], 16;" :: "r"(s), "l"(g));
}
#define CPA_COMMIT() asm volatile("cp.async.commit_group;" ::: "memory")
#define CPA_WAIT(n)  asm volatile("cp.async.wait_group %0;" :: "n"(n) : "memory")

// ===========================================================================
// Tiled GEMM core (R8): block = 64 tokens x 256 cols, 256 threads, 2 blocks/SM.
// Thread tile: 8 tokens x 8 cols as two split quads (cA..cA+3, cA+128..cA+131).
// ===========================================================================
#define GDECL \
    extern __shared__ float smem[]; \
    float* xs = smem; \
    float* ws = smem + NS * BK * GTOK; \
    const unsigned int xs_u = (unsigned int)__cvta_generic_to_shared(xs); \
    const unsigned int ws_u = (unsigned int)__cvta_generic_to_shared(ws); \
    const int tid = threadIdx.x; \
    const int t0  = (tid >> 5) * 8; \
    const int cA  = (tid & 31) * 4; \
    const int v   = blockIdx.y; \
    const int n0  = blockIdx.x * GTOK; \
    u64 acc[8][4]; \
    (void)v;

#define GCOL(c) (cA + ((c) & 3) + (((c) >> 2) * 128))

#define GZERO() do { \
    _Pragma("unroll") for (int _c = 0; _c < 8; ++_c) \
    _Pragma("unroll") for (int _t = 0; _t < 4; ++_t) acc[_c][_t] = 0ull; \
} while (0)

#define ISSUE(APTR, WPTR, WS_, k0, buf) do { \
    { int kr = tid >> 4, cc = tid & 15; \
      cpa16(xs_u + (((buf) * BK + kr) * GTOK + cc * 4) * 4, \
            (APTR) + (size_t)((k0) + kr) * NTOK + cc * 4); } \
    _Pragma("unroll") \
    for (int s2 = 0; s2 < 4; ++s2) { \
      int ci = tid + s2 * 256; int kr = ci >> 6, cc = ci & 63; \
      cpa16(ws_u + (((buf) * BK + kr) * NH + cc * 4) * 4, \
            (WPTR) + (size_t)((k0) + kr) * (WS_) + cc * 4); } \
} while (0)

#define GCHUNK(buf) do { \
    const float* xr = xs + (buf) * BK * GTOK + t0; \
    const float* wr = ws + (buf) * BK * NH + cA; \
    _Pragma("unroll") \
    for (int kk = 0; kk < BK; ++kk) { \
        float4 xa = *(const float4*)(xr + kk * GTOK); \
        float4 xb = *(const float4*)(xr + kk * GTOK + 4); \
        float4 wa = *(const float4*)(wr + kk * NH); \
        float4 wb = *(const float4*)(wr + kk * NH + 128); \
        u64 xp0 = pk2(xa.x, xa.y), xp1 = pk2(xa.z, xa.w); \
        u64 xp2 = pk2(xb.x, xb.y), xp3 = pk2(xb.z, xb.w); \
        u64 q; \
        q = pk2(wa.x, wa.x); fm2(acc[0][0], q, xp0); fm2(acc[0][1], q, xp1); fm2(acc[0][2], q, xp2); fm2(acc[0][3], q, xp3); \
        q = pk2(wa.y, wa.y); fm2(acc[1][0], q, xp0); fm2(acc[1][1], q, xp1); fm2(acc[1][2], q, xp2); fm2(acc[1][3], q, xp3); \
        q = pk2(wa.z, wa.z); fm2(acc[2][0], q, xp0); fm2(acc[2][1], q, xp1); fm2(acc[2][2], q, xp2); fm2(acc[2][3], q, xp3); \
        q = pk2(wa.w, wa.w); fm2(acc[3][0], q, xp0); fm2(acc[3][1], q, xp1); fm2(acc[3][2], q, xp2); fm2(acc[3][3], q, xp3); \
        q = pk2(wb.x, wb.x); fm2(acc[4][0], q, xp0); fm2(acc[4][1], q, xp1); fm2(acc[4][2], q, xp2); fm2(acc[4][3], q, xp3); \
        q = pk2(wb.y, wb.y); fm2(acc[5][0], q, xp0); fm2(acc[5][1], q, xp1); fm2(acc[5][2], q, xp2); fm2(acc[5][3], q, xp3); \
        q = pk2(wb.z, wb.z); fm2(acc[6][0], q, xp0); fm2(acc[6][1], q, xp1); fm2(acc[6][2], q, xp2); fm2(acc[6][3], q, xp3); \
        q = pk2(wb.w, wb.w); fm2(acc[7][0], q, xp0); fm2(acc[7][1], q, xp1); fm2(acc[7][2], q, xp2); fm2(acc[7][3], q, xp3); \
    } \
} while (0)

#define GRUN(APTR, WPTR, WS_, KN) do { \
    const int nkc = (KN) / BK; \
    _Pragma("unroll") \
    for (int p = 0; p < NS - 1; ++p) { \
        if (p < nkc) { ISSUE(APTR, WPTR, WS_, p * BK, p); CPA_COMMIT(); } \
    } \
    for (int kc = 0; kc < nkc; ++kc) { \
        CPA_WAIT(NS - 2); \
        __syncthreads(); \
        if (kc + NS - 1 < nkc) { \
            ISSUE(APTR, WPTR, WS_, (kc + NS - 1) * BK, (kc + NS - 1) % NS); \
            CPA_COMMIT(); \
        } \
        GCHUNK(kc % NS); \
    } \
} while (0)

#define GEPI(OUTP, BIASP, OP) do { \
    _Pragma("unroll") \
    for (int c = 0; c < 8; ++c) { \
        int col = GCOL(c); float bb = (BIASP)[col]; \
        float2 p0 = up2(acc[c][0]), p1 = up2(acc[c][1]); \
        float2 p2 = up2(acc[c][2]), p3 = up2(acc[c][3]); \
        float* d = (OUTP) + (size_t)col * NTOK + n0 + t0; \
        *(float4*)d       = make_float4(OP(p0.x + bb), OP(p0.y + bb), OP(p1.x + bb), OP(p1.y + bb)); \
        *(float4*)(d + 4) = make_float4(OP(p2.x + bb), OP(p2.y + bb), OP(p3.x + bb), OP(p3.y + bb)); \
    } \
} while (0)

// ---------------------------------------------------------------------------
// Kernel 0: context projection
// ---------------------------------------------------------------------------
__global__ void ctx_kernel(const float* __restrict__ ctx, const float* __restrict__ wctx)
{
    int b = blockIdx.x;
    int h = threadIdx.x;
    float acc = 0.f;
    for (int c = 0; c < NC; ++c)
        acc += ctx[b * NC + c] * wctx[c * NH + h];
    g_ctxp[b * NH + h] = acc;
}

// ---------------------------------------------------------------------------
// Kernel: transpose x[n][v][d] -> g_xT[v][d][n]
// ---------------------------------------------------------------------------
__global__ void xt_kernel(const float* __restrict__ x)
{
    __shared__ float s[64 * SP];
    const int v  = blockIdx.y;
    const int n0 = blockIdx.x * GT;
    const int tid = threadIdx.x;

#pragma unroll
    for (int r = 0; r < 8; ++r) {
        int idx = tid + r * 256;
        int t  = idx >> 4;
        int dq = idx & 15;
        float4 val = *(const float4*)(x + (size_t)(n0 + t) * 1024 + v * 64 + dq * 4);
        s[(dq * 4 + 0) * SP + t] = val.x;
        s[(dq * 4 + 1) * SP + t] = val.y;
        s[(dq * 4 + 2) * SP + t] = val.z;
        s[(dq * 4 + 3) * SP + t] = val.w;
    }
    __syncthreads();
#pragma unroll
    for (int r = 0; r < 8; ++r) {
        int idx = tid + r * 256;
        int d  = idx >> 5;
        int tq = idx & 31;
        float4 o = *(const float4*)(s + d * SP + tq * 4);
        *(float4*)(g_xT + ((size_t)v * ND + d) * NTOK + n0 + tq * 4) = o;
    }
}

// ---------------------------------------------------------------------------
// Kernel: wg skip residual = flat @ skip_w + skb -> g_wres[n][16]
// Thread = token; x loads coalesced from g_xT; weights broadcast.
// ---------------------------------------------------------------------------
__global__ __launch_bounds__(128, 8)
void skres_kernel(const float* __restrict__ skw, const float* __restrict__ skb)
{
    const int n = blockIdx.x * 128 + threadIdx.x;
    float acc[16];
#pragma unroll
    for (int j = 0; j < 16; ++j) acc[j] = skb[j];

#pragma unroll 4
    for (int k = 0; k < 1024; ++k) {
        float xv = g_xT[(size_t)k * NTOK + n];
        const float4* wr = (const float4*)(skw + (size_t)k * NV);
        float4 w0 = wr[0], w1 = wr[1], w2 = wr[2], w3 = wr[3];
        acc[0]  += xv * w0.x; acc[1]  += xv * w0.y; acc[2]  += xv * w0.z; acc[3]  += xv * w0.w;
        acc[4]  += xv * w1.x; acc[5]  += xv * w1.y; acc[6]  += xv * w1.z; acc[7]  += xv * w1.w;
        acc[8]  += xv * w2.x; acc[9]  += xv * w2.y; acc[10] += xv * w2.z; acc[11] += xv * w2.w;
        acc[12] += xv * w3.x; acc[13] += xv * w3.y; acc[14] += xv * w3.z; acc[15] += xv * w3.w;
    }

    float* dst = g_wres + (size_t)n * NV;
    *(float4*)(dst)      = make_float4(acc[0],  acc[1],  acc[2],  acc[3]);
    *(float4*)(dst + 4)  = make_float4(acc[4],  acc[5],  acc[6],  acc[7]);
    *(float4*)(dst + 8)  = make_float4(acc[8],  acc[9],  acc[10], acc[11]);
    *(float4*)(dst + 12) = make_float4(acc[12], acc[13], acc[14], acc[15]);
}

// ---------------------------------------------------------------------------
// Kernel: wg fc1 via pipelined GEMM. A = g_xT [1024][8192], W = wg_fc1_w.
// Epilogue: + fc1b + ctx, elu -> g_wh1[c][n].
// ---------------------------------------------------------------------------
__global__ __launch_bounds__(256, 2)
void wgfc1_kernel(const float* __restrict__ fc1w, const float* __restrict__ fc1b)
{
    GDECL;
    const float* A = g_xT + n0;

    GZERO();
    GRUN(A, fc1w, NH, 1024);

    const int b = n0 >> 8;   // 64 | 256 so block lies in one batch
#pragma unroll
    for (int c = 0; c < 8; ++c) {
        int col = GCOL(c);
        float bb = fc1b[col] + g_ctxp[b * NH + col];
        float2 p0 = up2(acc[c][0]), p1 = up2(acc[c][1]);
        float2 p2 = up2(acc[c][2]), p3 = up2(acc[c][3]);
        float* d = g_wh1 + (size_t)col * NTOK + n0 + t0;
        *(float4*)d       = make_float4(elu_f(p0.x + bb), elu_f(p0.y + bb), elu_f(p1.x + bb), elu_f(p1.y + bb));
        *(float4*)(d + 4) = make_float4(elu_f(p2.x + bb), elu_f(p2.y + bb), elu_f(p3.x + bb), elu_f(p3.y + bb));
    }
}

// ---------------------------------------------------------------------------
// Kernel 1: weight GRN rest: fc2 + glu + LN + softmax.
// h1 from g_wh1, residual from g_wres.
// ---------------------------------------------------------------------------
#define GSTEP(ACC) do { \
    u64 _xp; \
    _xp = pk2(xs0, xs0); fm2(ACC[0][0], wA.x, _xp); fm2(ACC[0][1], wA.y, _xp); fm2(ACC[0][2], wB.x, _xp); fm2(ACC[0][3], wB.y, _xp); \
    _xp = pk2(xs1, xs1); fm2(ACC[1][0], wA.x, _xp); fm2(ACC[1][1], wA.y, _xp); fm2(ACC[1][2], wB.x, _xp); fm2(ACC[1][3], wB.y, _xp); \
    _xp = pk2(xs2, xs2); fm2(ACC[2][0], wA.x, _xp); fm2(ACC[2][1], wA.y, _xp); fm2(ACC[2][2], wB.x, _xp); fm2(ACC[2][3], wB.y, _xp); \
    _xp = pk2(xs3, xs3); fm2(ACC[3][0], wA.x, _xp); fm2(ACC[3][1], wA.y, _xp); fm2(ACC[3][2], wB.x, _xp); fm2(ACC[3][3], wB.y, _xp); \
} while (0)

#define ZERO44(ACC) do { \
    _Pragma("unroll") for (int _i = 0; _i < 4; ++_i) \
    _Pragma("unroll") for (int _j = 0; _j < 4; ++_j) ACC[_i][_j] = 0ull; \
} while (0)

__global__ __launch_bounds__(NTH, 1)
void wg_kernel(const float* __restrict__ fc2w, const float* __restrict__ fc2b,
               const float* __restrict__ gluw, const float* __restrict__ glub,
               const float* __restrict__ lng,  const float* __restrict__ lnb,
               float* __restrict__ outw)
{
    extern __shared__ float sm[];
    float* ash = sm;                       // [256][PAD]  h1 from g_wh1
    float* bsh = ash + 256 * PAD;          // [256][PAD]
    float* rsh = bsh + 256 * PAD;          // [64][16]
    float* gsh = rsh + 64 * 16;            // [64][32]

    const int tid  = threadIdx.x;
    const int warp = tid >> 5, lane = tid & 31;
    const int t0 = warp * 4;
    const int c0 = lane * 8;
    const int n0 = blockIdx.x * TT;

    // ---- stage 1: load h1 from g_wh1 and residual from g_wres ----
    for (int i = tid; i < 256 * 16; i += NTH) {
        int c = i >> 4, tq = i & 15;
        float4 u = *(const float4*)(g_wh1 + (size_t)c * NTOK + n0 + tq * 4);
        ash[c * PAD + tq * 4 + 0] = u.x;
        ash[c * PAD + tq * 4 + 1] = u.y;
        ash[c * PAD + tq * 4 + 2] = u.z;
        ash[c * PAD + tq * 4 + 3] = u.w;
    }
    if (tid < 256) {
        float4 u = *(const float4*)(g_wres + (size_t)n0 * NV + tid * 4);
        *(float4*)(rsh + tid * 4) = u;   // rsh[t][j] contiguous = g_wres rows
    }
    __syncthreads();

    // ---- stage 2: h2 = h1 @ fc2 + b2 -> bsh ----
    u64 acc[4][4];
    ZERO44(acc);
    {
        const float* W2 = fc2w + c0;
#pragma unroll 2
        for (int k = 0; k < NH; ++k) {
            ulonglong2 wA = *(const ulonglong2*)(W2 + (size_t)k * NH);
            ulonglong2 wB = *(const ulonglong2*)(W2 + (size_t)k * NH + 4);
            float xs0 = ash[k * PAD + t0 + 0];
            float xs1 = ash[k * PAD + t0 + 1];
            float xs2 = ash[k * PAD + t0 + 2];
            float xs3 = ash[k * PAD + t0 + 3];
            GSTEP(acc);
        }
#pragma unroll
        for (int j = 0; j < 4; ++j) {
            int ca = c0 + 2 * j, cb = ca + 1;
            float ba = fc2b[ca], bb = fc2b[cb];
#pragma unroll
            for (int i = 0; i < 4; ++i) {
                float2 p = up2(acc[i][j]);
                bsh[ca * PAD + t0 + i] = p.x + ba;
                bsh[cb * PAD + t0 + i] = p.y + bb;
            }
        }
    }
    __syncthreads();

    // ---- stage 3: g = h2 @ glu_w + glu_b (K=256, 32 cols) ----
    {
        float a3[4] = {0.f, 0.f, 0.f, 0.f};
#pragma unroll 4
        for (int k = 0; k < NH; ++k) {
            float w = gluw[k * 32 + lane];
            a3[0] += bsh[k * PAD + t0 + 0] * w;
            a3[1] += bsh[k * PAD + t0 + 1] * w;
            a3[2] += bsh[k * PAD + t0 + 2] * w;
            a3[3] += bsh[k * PAD + t0 + 3] * w;
        }
        float gb = glub[lane];
#pragma unroll
        for (int i = 0; i < 4; ++i)
            gsh[(t0 + i) * 32 + lane] = a3[i] + gb;
    }
    __syncthreads();

    // ---- stage 4: GLU + residual + LN(16) + softmax(16) ----
    if (tid < TT) {
        int t = tid;
        float h[NV];
        float mu = 0.f;
#pragma unroll
        for (int v = 0; v < NV; ++v) {
            float a  = gsh[t * 32 + v];
            float bb = gsh[t * 32 + 16 + v];
            h[v] = a * sigm_f(bb) + rsh[t * 16 + v];
            mu += h[v];
        }
        mu *= (1.f / 16.f);
        float var = 0.f;
#pragma unroll
        for (int v = 0; v < NV; ++v) { float d = h[v] - mu; var += d * d; }
        var *= (1.f / 16.f);
        float rstd = rsqrtf(var + 1e-5f);
        float y[NV], m = -1e30f;
#pragma unroll
        for (int v = 0; v < NV; ++v) {
            y[v] = (h[v] - mu) * rstd * lng[v] + lnb[v];
            m = fmaxf(m, y[v]);
        }
        float s = 0.f;
#pragma unroll
        for (int v = 0; v < NV; ++v) { y[v] = __expf(y[v] - m); s += y[v]; }
        float inv = 1.f / s;
#pragma unroll
        for (int v = 0; v < NV; ++v)
            outw[(n0 + t) * NV + v] = y[v] * inv;
    }
}

// ---------------------------------------------------------------------------
// Kernel 2a: h1 = elu(x @ fc1 + b1), res = x @ skip + bs   (K = 64)
// ---------------------------------------------------------------------------
__global__ __launch_bounds__(256, 2)
void fc1skip_kernel(const float* __restrict__ fc1w, const float* __restrict__ fc1b,
                    const float* __restrict__ skw,  const float* __restrict__ skb)
{
    GDECL;
    const float* A  = g_xT + (size_t)v * ND * NTOK + n0;
    const float* W1 = fc1w + (size_t)v * ND * NH;
    const float* W2 = skw  + (size_t)v * ND * NH;

    GZERO();
    GRUN(A, W1, NH, ND);
    GEPI(g_h1 + (size_t)v * NH * NTOK, fc1b + v * NH, elu_f);

    GZERO();
    GRUN(A, W2, NH, ND);
    GEPI(g_res + (size_t)v * NH * NTOK, skb + v * NH, idf);
}

// ---------------------------------------------------------------------------
// Kernel 2b: h2 = h1 @ fc2 + b2   (K = 256)
// ---------------------------------------------------------------------------
__global__ __launch_bounds__(256, 2)
void fc2_kernel(const float* __restrict__ fc2w, const float* __restrict__ fc2b)
{
    GDECL;
    const float* A = g_h1 + (size_t)v * NH * NTOK + n0;
    const float* W = fc2w + (size_t)v * NH * NH;

    GZERO();
    GRUN(A, W, NH, NH);
    GEPI(g_h2 + (size_t)v * NH * NTOK, fc2b + v * NH, idf);
}

// ---------------------------------------------------------------------------
// Kernel 2c-1: a-half of GLU -> g_a   (K = 256)
// ---------------------------------------------------------------------------
__global__ __launch_bounds__(256, 2)
void glu_a_kernel(const float* __restrict__ gluw, const float* __restrict__ glub)
{
    GDECL;
    const float* A = g_h2 + (size_t)v * NH * NTOK + n0;
    const float* W = gluw + (size_t)v * NH * 512;

    GZERO();
    GRUN(A, W, 512, NH);
    GEPI(g_a + (size_t)v * NH * NTOK, glub + v * 512, idf);
}

// ---------------------------------------------------------------------------
// Kernel 2c-2: b-half + combine: hv = a * sigm(b) + res -> g_hv [n][v][c]
// ---------------------------------------------------------------------------
__global__ __launch_bounds__(256, 2)
void glu_b_kernel(const float* __restrict__ gluw, const float* __restrict__ glub)
{
    GDECL;
    const float* A = g_h2 + (size_t)v * NH * NTOK + n0;
    const float* W = gluw + (size_t)v * NH * 512 + 256;

    GZERO();
    GRUN(A, W, 512, NH);

#pragma unroll
    for (int c = 0; c < 8; ++c) {
        int col = GCOL(c);
        float bb = glub[v * 512 + 256 + col];
        const float* ap = g_a   + ((size_t)v * NH + col) * NTOK + n0 + t0;
        const float* rp = g_res + ((size_t)v * NH + col) * NTOK + n0 + t0;
        float4 a0 = *(const float4*)ap, a1 = *(const float4*)(ap + 4);
        float4 r0 = *(const float4*)rp, r1 = *(const float4*)(rp + 4);
        float2 p0 = up2(acc[c][0]), p1 = up2(acc[c][1]);
        float2 p2 = up2(acc[c][2]), p3 = up2(acc[c][3]);
        float h0 = a0.x * sigm_f(p0.x + bb) + r0.x;
        float h1 = a0.y * sigm_f(p0.y + bb) + r0.y;
        float h2 = a0.z * sigm_f(p1.x + bb) + r0.z;
        float h3 = a0.w * sigm_f(p1.y + bb) + r0.w;
        float h4 = a1.x * sigm_f(p2.x + bb) + r1.x;
        float h5 = a1.y * sigm_f(p2.y + bb) + r1.y;
        float h6 = a1.z * sigm_f(p3.x + bb) + r1.z;
        float h7 = a1.w * sigm_f(p3.y + bb) + r1.w;
        acc[c][0] = pk2(h0, h1); acc[c][1] = pk2(h2, h3);
        acc[c][2] = pk2(h4, h5); acc[c][3] = pk2(h6, h7);
    }

#pragma unroll
    for (int tp = 0; tp < 4; ++tp) {
        float2 q0 = up2(acc[0][tp]), q1 = up2(acc[1][tp]);
        float2 q2 = up2(acc[2][tp]), q3 = up2(acc[3][tp]);
        float2 q4 = up2(acc[4][tp]), q5 = up2(acc[5][tp]);
        float2 q6 = up2(acc[6][tp]), q7 = up2(acc[7][tp]);
        float* dA = g_hv + (size_t)(n0 + t0 + 2 * tp)     * (NV * NH) + v * NH;
        float* dB = g_hv + (size_t)(n0 + t0 + 2 * tp + 1) * (NV * NH) + v * NH;
        *(float4*)(dA + cA)       = make_float4(q0.x, q1.x, q2.x, q3.x);
        *(float4*)(dA + cA + 128) = make_float4(q4.x, q5.x, q6.x, q7.x);
        *(float4*)(dB + cA)       = make_float4(q0.y, q1.y, q2.y, q3.y);
        *(float4*)(dB + cA + 128) = make_float4(q4.y, q5.y, q6.y, q7.y);
    }
}

// ---------------------------------------------------------------------------
// Kernel 3: per-token LN(256) per v + weight scale + sum over v -> selected
// ---------------------------------------------------------------------------
__global__ void combine_kernel(const float* __restrict__ lng, const float* __restrict__ lnb,
                               const float* __restrict__ wts, float* __restrict__ out_sel)
{
    __shared__ float s_part[8 * 260];
    const int n = blockIdx.x;
    const int tid = threadIdx.x;
    const int w = tid >> 5, lane = tid & 31;

    float psum[8];
#pragma unroll
    for (int j = 0; j < 8; ++j) psum[j] = 0.f;

#pragma unroll
    for (int vv = 0; vv < 2; ++vv) {
        int v = w * 2 + vv;
        const float* p = g_hv + (size_t)n * (NV * NH) + v * NH + lane * 8;
        float4 u0 = *(const float4*)p, u1 = *(const float4*)(p + 4);
        float uu[8] = {u0.x, u0.y, u0.z, u0.w, u1.x, u1.y, u1.z, u1.w};
        float s = 0.f, s2 = 0.f;
#pragma unroll
        for (int j = 0; j < 8; ++j) { s += uu[j]; s2 += uu[j] * uu[j]; }
#pragma unroll
        for (int off = 16; off > 0; off >>= 1) {
            s  += __shfl_xor_sync(0xffffffffu, s,  off);
            s2 += __shfl_xor_sync(0xffffffffu, s2, off);
        }
        float mu   = s * (1.f / 256.f);
        float var  = s2 * (1.f / 256.f) - mu * mu;
        float rstd = rsqrtf(var + 1e-5f);
        float wv = wts[n * NV + v];
#pragma unroll
        for (int j = 0; j < 8; ++j) {
            int c = lane * 8 + j;
            float y = (uu[j] - mu) * rstd * lng[v * NH + c] + lnb[v * NH + c];
            psum[j] += y * wv;
        }
    }

    *(float4*)(s_part + w * 260 + lane * 8)     = make_float4(psum[0], psum[1], psum[2], psum[3]);
    *(float4*)(s_part + w * 260 + lane * 8 + 4) = make_float4(psum[4], psum[5], psum[6], psum[7]);
    __syncthreads();

    float s = 0.f;
#pragma unroll
    for (int w8 = 0; w8 < 8; ++w8) s += s_part[w8 * 260 + tid];
    out_sel[(size_t)n * NH + tid] = s;
}

// ---------------------------------------------------------------------------
extern "C" void kernel_launch(void* const* d_in, const int* in_sizes, int n_in,
                              void* d_out, int out_size)
{
    const float* x        = (const float*)d_in[0];
    const float* context  = (const float*)d_in[1];
    const float* vg_fc1_w = (const float*)d_in[2];
    const float* vg_fc1_b = (const float*)d_in[3];
    const float* vg_fc2_w = (const float*)d_in[4];
    const float* vg_fc2_b = (const float*)d_in[5];
    const float* vg_glu_w = (const float*)d_in[6];
    const float* vg_glu_b = (const float*)d_in[7];
    const float* vg_skip_w= (const float*)d_in[8];
    const float* vg_skip_b= (const float*)d_in[9];
    const float* vg_ln_g  = (const float*)d_in[10];
    const float* vg_ln_b  = (const float*)d_in[11];
    const float* wg_fc1_w = (const float*)d_in[12];
    const float* wg_fc1_b = (const float*)d_in[13];
    const float* wg_ctx_w = (const float*)d_in[14];
    const float* wg_fc2_w = (const float*)d_in[15];
    const float* wg_fc2_b = (const float*)d_in[16];
    const float* wg_glu_w = (const float*)d_in[17];
    const float* wg_glu_b = (const float*)d_in[18];
    const float* wg_skip_w= (const float*)d_in[19];
    const float* wg_skip_b= (const float*)d_in[20];
    const float* wg_ln_g  = (const float*)d_in[21];
    const float* wg_ln_b  = (const float*)d_in[22];

    float* out      = (float*)d_out;
    float* out_sel  = out;
    float* out_wts  = out + (size_t)NTOK * NH;

    const int WG_SMEM = (2 * 256 * PAD + 64 * 16 + 64 * 32) * 4;   // ~145KB
    const int G_SMEM  = NS * BK * (GTOK + NH) * 4;                 // 80KB/block
    cudaFuncSetAttribute(wg_kernel,      cudaFuncAttributeMaxDynamicSharedMemorySize, WG_SMEM);
    cudaFuncSetAttribute(wgfc1_kernel,   cudaFuncAttributeMaxDynamicSharedMemorySize, G_SMEM);
    cudaFuncSetAttribute(fc1skip_kernel, cudaFuncAttributeMaxDynamicSharedMemorySize, G_SMEM);
    cudaFuncSetAttribute(fc2_kernel,     cudaFuncAttributeMaxDynamicSharedMemorySize, G_SMEM);
    cudaFuncSetAttribute(glu_a_kernel,   cudaFuncAttributeMaxDynamicSharedMemorySize, G_SMEM);
    cudaFuncSetAttribute(glu_b_kernel,   cudaFuncAttributeMaxDynamicSharedMemorySize, G_SMEM);

    const dim3 xgrid(NTOK / GT, NV);
    const dim3 ggrid(NTOK / GTOK, NV);

    ctx_kernel<<<32, NH>>>(context, wg_ctx_w);
    xt_kernel<<<xgrid, 256>>>(x);

    skres_kernel<<<NTOK / 128, 128>>>(wg_skip_w, wg_skip_b);
    wgfc1_kernel<<<dim3(NTOK / GTOK, 1), 256, G_SMEM>>>(wg_fc1_w, wg_fc1_b);
    wg_kernel<<<NTOK / TT, NTH, WG_SMEM>>>(
        wg_fc2_w, wg_fc2_b, wg_glu_w, wg_glu_b, wg_ln_g, wg_ln_b, out_wts);

    fc1skip_kernel<<<ggrid, 256, G_SMEM>>>(vg_fc1_w, vg_fc1_b, vg_skip_w, vg_skip_b);
    fc2_kernel<<<ggrid, 256, G_SMEM>>>(vg_fc2_w, vg_fc2_b);
    glu_a_kernel<<<ggrid, 256, G_SMEM>>>(vg_glu_w, vg_glu_b);
    glu_b_kernel<<<ggrid, 256, G_SMEM>>>(vg_glu_w, vg_glu_b);

    combine_kernel<<<NTOK, 256>>>(vg_ln_g, vg_ln_b, out_wts, out_sel);
}

// round 14
// speedup vs baseline: 1.0983x; 1.0983x over previous
#include <cuda_runtime.h>
#include <math.h>
#include <stdint.h>

// Problem constants
#define NTH   512
#define PAD   65
#define NV    16
#define ND    64
#define NH    256
#define NC    128
#define NTOK  8192
#define TT    64     // wg token tile
#define GT    128    // xt token tile
#define GTOK  64     // gemm token tile
#define BK    16     // gemm k-chunk
#define NS    4      // pipeline stages
#define SP    132    // xt smem pad

typedef unsigned long long u64;

// Scratch (device globals: allocation-free rule)
__device__ float g_ctxp[32 * NH];
__device__ float g_xT[NV * ND * NTOK];        // x transposed [v][d][n] == flat^T [k][n]
__device__ float g_h1[NV * NH * NTOK];        // elu(fc1) [v][c][n]
__device__ float g_res[NV * NH * NTOK];       // skip residual [v][c][n]
__device__ float g_h2[NV * NH * NTOK];        // fc2 out [v][c][n]
__device__ float g_a[NV * NH * NTOK];         // glu a-half [v][c][n]
__device__ float g_hv[NTOK * NV * NH];        // raw hv (pre-LN) [n][v][c]
__device__ float g_wh1[2 * NH * NTOK];        // wg fc1 partials [khalf][c][n]

__device__ __forceinline__ float elu_f(float x)  { return x > 0.f ? x : (__expf(x) - 1.f); }
__device__ __forceinline__ float sigm_f(float x) { return 1.f / (1.f + __expf(-x)); }
__device__ __forceinline__ float idf(float x)    { return x; }

// ---- packed fp32x2 helpers ----
__device__ __forceinline__ u64 pk2(float a, float b) {
    u64 r; asm("mov.b64 %0, {%1, %2};" : "=l"(r) : "f"(a), "f"(b)); return r;
}
__device__ __forceinline__ void fm2(u64& d, u64 a, u64 b) {
    asm("fma.rn.f32x2 %0, %1, %2, %0;" : "+l"(d) : "l"(a), "l"(b));
}
__device__ __forceinline__ float2 up2(u64 v) {
    float2 f; asm("mov.b64 {%0, %1}, %2;" : "=f"(f.x), "=f"(f.y) : "l"(v)); return f;
}

// ---- cp.async helpers ----
__device__ __forceinline__ void cpa16(unsigned int s, const void* g) {
    asm volatile("cp.async.cg.shared.global [%0], [%1], 16;" :: "r"(s), "l"(g));
}
#define CPA_COMMIT() asm volatile("cp.async.commit_group;" ::: "memory")
#define CPA_WAIT(n)  asm volatile("cp.async.wait_group %0;" :: "n"(n) : "memory")

// ===========================================================================
// Tiled GEMM core (R8): block = 64 tokens x 256 cols, 256 threads, 2 blocks/SM.
// Thread tile: 8 tokens x 8 cols as two split quads (cA..cA+3, cA+128..cA+131).
// ===========================================================================
#define GDECL \
    extern __shared__ float smem[]; \
    float* xs = smem; \
    float* ws = smem + NS * BK * GTOK; \
    const unsigned int xs_u = (unsigned int)__cvta_generic_to_shared(xs); \
    const unsigned int ws_u = (unsigned int)__cvta_generic_to_shared(ws); \
    const int tid = threadIdx.x; \
    const int t0  = (tid >> 5) * 8; \
    const int cA  = (tid & 31) * 4; \
    const int v   = blockIdx.y; \
    const int n0  = blockIdx.x * GTOK; \
    u64 acc[8][4]; \
    (void)v;

#define GCOL(c) (cA + ((c) & 3) + (((c) >> 2) * 128))

#define GZERO() do { \
    _Pragma("unroll") for (int _c = 0; _c < 8; ++_c) \
    _Pragma("unroll") for (int _t = 0; _t < 4; ++_t) acc[_c][_t] = 0ull; \
} while (0)

#define ISSUE(APTR, WPTR, WS_, k0, buf) do { \
    { int kr = tid >> 4, cc = tid & 15; \
      cpa16(xs_u + (((buf) * BK + kr) * GTOK + cc * 4) * 4, \
            (APTR) + (size_t)((k0) + kr) * NTOK + cc * 4); } \
    _Pragma("unroll") \
    for (int s2 = 0; s2 < 4; ++s2) { \
      int ci = tid + s2 * 256; int kr = ci >> 6, cc = ci & 63; \
      cpa16(ws_u + (((buf) * BK + kr) * NH + cc * 4) * 4, \
            (WPTR) + (size_t)((k0) + kr) * (WS_) + cc * 4); } \
} while (0)

#define GCHUNK(buf) do { \
    const float* xr = xs + (buf) * BK * GTOK + t0; \
    const float* wr = ws + (buf) * BK * NH + cA; \
    _Pragma("unroll") \
    for (int kk = 0; kk < BK; ++kk) { \
        float4 xa = *(const float4*)(xr + kk * GTOK); \
        float4 xb = *(const float4*)(xr + kk * GTOK + 4); \
        float4 wa = *(const float4*)(wr + kk * NH); \
        float4 wb = *(const float4*)(wr + kk * NH + 128); \
        u64 xp0 = pk2(xa.x, xa.y), xp1 = pk2(xa.z, xa.w); \
        u64 xp2 = pk2(xb.x, xb.y), xp3 = pk2(xb.z, xb.w); \
        u64 q; \
        q = pk2(wa.x, wa.x); fm2(acc[0][0], q, xp0); fm2(acc[0][1], q, xp1); fm2(acc[0][2], q, xp2); fm2(acc[0][3], q, xp3); \
        q = pk2(wa.y, wa.y); fm2(acc[1][0], q, xp0); fm2(acc[1][1], q, xp1); fm2(acc[1][2], q, xp2); fm2(acc[1][3], q, xp3); \
        q = pk2(wa.z, wa.z); fm2(acc[2][0], q, xp0); fm2(acc[2][1], q, xp1); fm2(acc[2][2], q, xp2); fm2(acc[2][3], q, xp3); \
        q = pk2(wa.w, wa.w); fm2(acc[3][0], q, xp0); fm2(acc[3][1], q, xp1); fm2(acc[3][2], q, xp2); fm2(acc[3][3], q, xp3); \
        q = pk2(wb.x, wb.x); fm2(acc[4][0], q, xp0); fm2(acc[4][1], q, xp1); fm2(acc[4][2], q, xp2); fm2(acc[4][3], q, xp3); \
        q = pk2(wb.y, wb.y); fm2(acc[5][0], q, xp0); fm2(acc[5][1], q, xp1); fm2(acc[5][2], q, xp2); fm2(acc[5][3], q, xp3); \
        q = pk2(wb.z, wb.z); fm2(acc[6][0], q, xp0); fm2(acc[6][1], q, xp1); fm2(acc[6][2], q, xp2); fm2(acc[6][3], q, xp3); \
        q = pk2(wb.w, wb.w); fm2(acc[7][0], q, xp0); fm2(acc[7][1], q, xp1); fm2(acc[7][2], q, xp2); fm2(acc[7][3], q, xp3); \
    } \
} while (0)

#define GRUN(APTR, WPTR, WS_, KN) do { \
    const int nkc = (KN) / BK; \
    _Pragma("unroll") \
    for (int p = 0; p < NS - 1; ++p) { \
        if (p < nkc) { ISSUE(APTR, WPTR, WS_, p * BK, p); CPA_COMMIT(); } \
    } \
    for (int kc = 0; kc < nkc; ++kc) { \
        CPA_WAIT(NS - 2); \
        __syncthreads(); \
        if (kc + NS - 1 < nkc) { \
            ISSUE(APTR, WPTR, WS_, (kc + NS - 1) * BK, (kc + NS - 1) % NS); \
            CPA_COMMIT(); \
        } \
        GCHUNK(kc % NS); \
    } \
} while (0)

#define GEPI(OUTP, BIASP, OP) do { \
    _Pragma("unroll") \
    for (int c = 0; c < 8; ++c) { \
        int col = GCOL(c); float bb = (BIASP)[col]; \
        float2 p0 = up2(acc[c][0]), p1 = up2(acc[c][1]); \
        float2 p2 = up2(acc[c][2]), p3 = up2(acc[c][3]); \
        float* d = (OUTP) + (size_t)col * NTOK + n0 + t0; \
        *(float4*)d       = make_float4(OP(p0.x + bb), OP(p0.y + bb), OP(p1.x + bb), OP(p1.y + bb)); \
        *(float4*)(d + 4) = make_float4(OP(p2.x + bb), OP(p2.y + bb), OP(p3.x + bb), OP(p3.y + bb)); \
    } \
} while (0)

// ---------------------------------------------------------------------------
// Kernel 0: context projection
// ---------------------------------------------------------------------------
__global__ void ctx_kernel(const float* __restrict__ ctx, const float* __restrict__ wctx)
{
    int b = blockIdx.x;
    int h = threadIdx.x;
    float acc = 0.f;
    for (int c = 0; c < NC; ++c)
        acc += ctx[b * NC + c] * wctx[c * NH + h];
    g_ctxp[b * NH + h] = acc;
}

// ---------------------------------------------------------------------------
// Kernel: transpose x[n][v][d] -> g_xT[v][d][n]
// ---------------------------------------------------------------------------
__global__ void xt_kernel(const float* __restrict__ x)
{
    __shared__ float s[64 * SP];
    const int v  = blockIdx.y;
    const int n0 = blockIdx.x * GT;
    const int tid = threadIdx.x;

#pragma unroll
    for (int r = 0; r < 8; ++r) {
        int idx = tid + r * 256;
        int t  = idx >> 4;
        int dq = idx & 15;
        float4 val = *(const float4*)(x + (size_t)(n0 + t) * 1024 + v * 64 + dq * 4);
        s[(dq * 4 + 0) * SP + t] = val.x;
        s[(dq * 4 + 1) * SP + t] = val.y;
        s[(dq * 4 + 2) * SP + t] = val.z;
        s[(dq * 4 + 3) * SP + t] = val.w;
    }
    __syncthreads();
#pragma unroll
    for (int r = 0; r < 8; ++r) {
        int idx = tid + r * 256;
        int d  = idx >> 5;
        int tq = idx & 31;
        float4 o = *(const float4*)(s + d * SP + tq * 4);
        *(float4*)(g_xT + ((size_t)v * ND + d) * NTOK + n0 + tq * 4) = o;
    }
}

// ---------------------------------------------------------------------------
// Kernel: wg fc1 K-split GEMM. blockIdx.y = K-half (512 each).
// Writes RAW partial sums to g_wh1[khalf][c][n]; bias+ctx+elu applied in wg.
// ---------------------------------------------------------------------------
__global__ __launch_bounds__(256, 2)
void wgfc1_kernel(const float* __restrict__ fc1w)
{
    GDECL;
    const int kh = blockIdx.y;
    const float* A = g_xT + (size_t)kh * 512 * NTOK + n0;
    const float* W = fc1w + (size_t)kh * 512 * NH;

    GZERO();
    GRUN(A, W, NH, 512);

#pragma unroll
    for (int c = 0; c < 8; ++c) {
        int col = GCOL(c);
        float2 p0 = up2(acc[c][0]), p1 = up2(acc[c][1]);
        float2 p2 = up2(acc[c][2]), p3 = up2(acc[c][3]);
        float* d = g_wh1 + ((size_t)kh * NH + col) * NTOK + n0 + t0;
        *(float4*)d       = make_float4(p0.x, p0.y, p1.x, p1.y);
        *(float4*)(d + 4) = make_float4(p2.x, p2.y, p3.x, p3.y);
    }
}

// ---------------------------------------------------------------------------
// Kernel 1: weight GRN: skip residual (smem-staged skw) + fc2 + glu + LN + softmax.
// h1 = elu(partial0 + partial1 + fc1b + ctx) from g_wh1.
// ---------------------------------------------------------------------------
#define GSTEP(ACC) do { \
    u64 _xp; \
    _xp = pk2(xs0, xs0); fm2(ACC[0][0], wA.x, _xp); fm2(ACC[0][1], wA.y, _xp); fm2(ACC[0][2], wB.x, _xp); fm2(ACC[0][3], wB.y, _xp); \
    _xp = pk2(xs1, xs1); fm2(ACC[1][0], wA.x, _xp); fm2(ACC[1][1], wA.y, _xp); fm2(ACC[1][2], wB.x, _xp); fm2(ACC[1][3], wB.y, _xp); \
    _xp = pk2(xs2, xs2); fm2(ACC[2][0], wA.x, _xp); fm2(ACC[2][1], wA.y, _xp); fm2(ACC[2][2], wB.x, _xp); fm2(ACC[2][3], wB.y, _xp); \
    _xp = pk2(xs3, xs3); fm2(ACC[3][0], wA.x, _xp); fm2(ACC[3][1], wA.y, _xp); fm2(ACC[3][2], wB.x, _xp); fm2(ACC[3][3], wB.y, _xp); \
} while (0)

#define ZERO44(ACC) do { \
    _Pragma("unroll") for (int _i = 0; _i < 4; ++_i) \
    _Pragma("unroll") for (int _j = 0; _j < 4; ++_j) ACC[_i][_j] = 0ull; \
} while (0)

__global__ __launch_bounds__(NTH, 1)
void wg_kernel(const float* __restrict__ x,
               const float* __restrict__ fc1b,
               const float* __restrict__ fc2w, const float* __restrict__ fc2b,
               const float* __restrict__ gluw, const float* __restrict__ glub,
               const float* __restrict__ skw,  const float* __restrict__ skb,
               const float* __restrict__ lng,  const float* __restrict__ lnb,
               float* __restrict__ outw)
{
    extern __shared__ float sm[];
    float* sx  = sm;                       // [128][PAD]
    float* ash = sx  + 128 * PAD;          // [256][PAD]  h1
    float* bsh = ash + 256 * PAD;          // [256][PAD]  h2
    float* rsh = bsh + 256 * PAD;          // [64][16]    residual
    float* gsh = rsh + 64 * 16;            // [64][32]    glu pre-act
    float* ssk = gsh + 64 * 32;            // [128][16]   skw chunk

    const int tid  = threadIdx.x;
    const int warp = tid >> 5, lane = tid & 31;
    const int t0 = warp * 4;
    const int c0 = lane * 8;
    const int n0 = blockIdx.x * TT;
    const int tR = tid >> 3, jR = tid & 7;

    float r0 = 0.f, r1 = 0.f;

    // ---- stage 1: residual = flat @ skip (K=1024, 8 k-tiles, skw staged) ----
    for (int kt = 0; kt < 8; ++kt) {
        for (int i = tid; i < TT * 128; i += NTH) {
            int t = i >> 7, k = i & 127;
            sx[k * PAD + t] = x[(size_t)(n0 + t) * 1024 + kt * 128 + k];
        }
        {   // stage skw chunk: 128 rows x 16 = 2048 floats, 4 per thread
            float4 w = *(const float4*)(skw + (size_t)kt * 128 * NV + tid * 4);
            *(float4*)(ssk + tid * 4) = w;
        }
        __syncthreads();
#pragma unroll 4
        for (int k = 0; k < 128; ++k) {
            float xv = sx[k * PAD + tR];
            r0 += xv * ssk[k * NV + jR];
            r1 += xv * ssk[k * NV + jR + 8];
        }
        __syncthreads();
    }
    rsh[tR * 16 + jR]     = r0 + skb[jR];
    rsh[tR * 16 + jR + 8] = r1 + skb[jR + 8];

    // ---- stage 1b: h1 = elu(partial0 + partial1 + fc1b + ctx) -> ash ----
    {
        const int b = n0 >> 8;
        for (int i = tid; i < 256 * 16; i += NTH) {
            int c = i >> 4, tq = i & 15;
            float4 u0 = *(const float4*)(g_wh1 + (size_t)c * NTOK + n0 + tq * 4);
            float4 u1 = *(const float4*)(g_wh1 + (size_t)(NH + c) * NTOK + n0 + tq * 4);
            float bb = fc1b[c] + g_ctxp[b * NH + c];
            ash[c * PAD + tq * 4 + 0] = elu_f(u0.x + u1.x + bb);
            ash[c * PAD + tq * 4 + 1] = elu_f(u0.y + u1.y + bb);
            ash[c * PAD + tq * 4 + 2] = elu_f(u0.z + u1.z + bb);
            ash[c * PAD + tq * 4 + 3] = elu_f(u0.w + u1.w + bb);
        }
    }
    __syncthreads();

    // ---- stage 2: h2 = h1 @ fc2 + b2 -> bsh ----
    u64 acc[4][4];
    ZERO44(acc);
    {
        const float* W2 = fc2w + c0;
#pragma unroll 2
        for (int k = 0; k < NH; ++k) {
            ulonglong2 wA = *(const ulonglong2*)(W2 + (size_t)k * NH);
            ulonglong2 wB = *(const ulonglong2*)(W2 + (size_t)k * NH + 4);
            float xs0 = ash[k * PAD + t0 + 0];
            float xs1 = ash[k * PAD + t0 + 1];
            float xs2 = ash[k * PAD + t0 + 2];
            float xs3 = ash[k * PAD + t0 + 3];
            GSTEP(acc);
        }
#pragma unroll
        for (int j = 0; j < 4; ++j) {
            int ca = c0 + 2 * j, cb = ca + 1;
            float ba = fc2b[ca], bb = fc2b[cb];
#pragma unroll
            for (int i = 0; i < 4; ++i) {
                float2 p = up2(acc[i][j]);
                bsh[ca * PAD + t0 + i] = p.x + ba;
                bsh[cb * PAD + t0 + i] = p.y + bb;
            }
        }
    }
    __syncthreads();

    // ---- stage 3: g = h2 @ glu_w + glu_b (K=256, 32 cols) ----
    {
        float a3[4] = {0.f, 0.f, 0.f, 0.f};
#pragma unroll 4
        for (int k = 0; k < NH; ++k) {
            float w = gluw[k * 32 + lane];
            a3[0] += bsh[k * PAD + t0 + 0] * w;
            a3[1] += bsh[k * PAD + t0 + 1] * w;
            a3[2] += bsh[k * PAD + t0 + 2] * w;
            a3[3] += bsh[k * PAD + t0 + 3] * w;
        }
        float gb = glub[lane];
#pragma unroll
        for (int i = 0; i < 4; ++i)
            gsh[(t0 + i) * 32 + lane] = a3[i] + gb;
    }
    __syncthreads();

    // ---- stage 4: GLU + residual + LN(16) + softmax(16) ----
    if (tid < TT) {
        int t = tid;
        float h[NV];
        float mu = 0.f;
#pragma unroll
        for (int v = 0; v < NV; ++v) {
            float a  = gsh[t * 32 + v];
            float bb = gsh[t * 32 + 16 + v];
            h[v] = a * sigm_f(bb) + rsh[t * 16 + v];
            mu += h[v];
        }
        mu *= (1.f / 16.f);
        float var = 0.f;
#pragma unroll
        for (int v = 0; v < NV; ++v) { float d = h[v] - mu; var += d * d; }
        var *= (1.f / 16.f);
        float rstd = rsqrtf(var + 1e-5f);
        float y[NV], m = -1e30f;
#pragma unroll
        for (int v = 0; v < NV; ++v) {
            y[v] = (h[v] - mu) * rstd * lng[v] + lnb[v];
            m = fmaxf(m, y[v]);
        }
        float s = 0.f;
#pragma unroll
        for (int v = 0; v < NV; ++v) { y[v] = __expf(y[v] - m); s += y[v]; }
        float inv = 1.f / s;
#pragma unroll
        for (int v = 0; v < NV; ++v)
            outw[(n0 + t) * NV + v] = y[v] * inv;
    }
}

// ---------------------------------------------------------------------------
// Kernel 2a: h1 = elu(x @ fc1 + b1), res = x @ skip + bs   (K = 64)
// ---------------------------------------------------------------------------
__global__ __launch_bounds__(256, 2)
void fc1skip_kernel(const float* __restrict__ fc1w, const float* __restrict__ fc1b,
                    const float* __restrict__ skw,  const float* __restrict__ skb)
{
    GDECL;
    const float* A  = g_xT + (size_t)v * ND * NTOK + n0;
    const float* W1 = fc1w + (size_t)v * ND * NH;
    const float* W2 = skw  + (size_t)v * ND * NH;

    GZERO();
    GRUN(A, W1, NH, ND);
    GEPI(g_h1 + (size_t)v * NH * NTOK, fc1b + v * NH, elu_f);

    GZERO();
    GRUN(A, W2, NH, ND);
    GEPI(g_res + (size_t)v * NH * NTOK, skb + v * NH, idf);
}

// ---------------------------------------------------------------------------
// Kernel 2b: h2 = h1 @ fc2 + b2   (K = 256)
// ---------------------------------------------------------------------------
__global__ __launch_bounds__(256, 2)
void fc2_kernel(const float* __restrict__ fc2w, const float* __restrict__ fc2b)
{
    GDECL;
    const float* A = g_h1 + (size_t)v * NH * NTOK + n0;
    const float* W = fc2w + (size_t)v * NH * NH;

    GZERO();
    GRUN(A, W, NH, NH);
    GEPI(g_h2 + (size_t)v * NH * NTOK, fc2b + v * NH, idf);
}

// ---------------------------------------------------------------------------
// Kernel 2c-1: a-half of GLU -> g_a   (K = 256)
// ---------------------------------------------------------------------------
__global__ __launch_bounds__(256, 2)
void glu_a_kernel(const float* __restrict__ gluw, const float* __restrict__ glub)
{
    GDECL;
    const float* A = g_h2 + (size_t)v * NH * NTOK + n0;
    const float* W = gluw + (size_t)v * NH * 512;

    GZERO();
    GRUN(A, W, 512, NH);
    GEPI(g_a + (size_t)v * NH * NTOK, glub + v * 512, idf);
}

// ---------------------------------------------------------------------------
// Kernel 2c-2: b-half + combine: hv = a * sigm(b) + res -> g_hv [n][v][c]
// ---------------------------------------------------------------------------
__global__ __launch_bounds__(256, 2)
void glu_b_kernel(const float* __restrict__ gluw, const float* __restrict__ glub)
{
    GDECL;
    const float* A = g_h2 + (size_t)v * NH * NTOK + n0;
    const float* W = gluw + (size_t)v * NH * 512 + 256;

    GZERO();
    GRUN(A, W, 512, NH);

#pragma unroll
    for (int c = 0; c < 8; ++c) {
        int col = GCOL(c);
        float bb = glub[v * 512 + 256 + col];
        const float* ap = g_a   + ((size_t)v * NH + col) * NTOK + n0 + t0;
        const float* rp = g_res + ((size_t)v * NH + col) * NTOK + n0 + t0;
        float4 a0 = *(const float4*)ap, a1 = *(const float4*)(ap + 4);
        float4 r0 = *(const float4*)rp, r1 = *(const float4*)(rp + 4);
        float2 p0 = up2(acc[c][0]), p1 = up2(acc[c][1]);
        float2 p2 = up2(acc[c][2]), p3 = up2(acc[c][3]);
        float h0 = a0.x * sigm_f(p0.x + bb) + r0.x;
        float h1 = a0.y * sigm_f(p0.y + bb) + r0.y;
        float h2 = a0.z * sigm_f(p1.x + bb) + r0.z;
        float h3 = a0.w * sigm_f(p1.y + bb) + r0.w;
        float h4 = a1.x * sigm_f(p2.x + bb) + r1.x;
        float h5 = a1.y * sigm_f(p2.y + bb) + r1.y;
        float h6 = a1.z * sigm_f(p3.x + bb) + r1.z;
        float h7 = a1.w * sigm_f(p3.y + bb) + r1.w;
        acc[c][0] = pk2(h0, h1); acc[c][1] = pk2(h2, h3);
        acc[c][2] = pk2(h4, h5); acc[c][3] = pk2(h6, h7);
    }

#pragma unroll
    for (int tp = 0; tp < 4; ++tp) {
        float2 q0 = up2(acc[0][tp]), q1 = up2(acc[1][tp]);
        float2 q2 = up2(acc[2][tp]), q3 = up2(acc[3][tp]);
        float2 q4 = up2(acc[4][tp]), q5 = up2(acc[5][tp]);
        float2 q6 = up2(acc[6][tp]), q7 = up2(acc[7][tp]);
        float* dA = g_hv + (size_t)(n0 + t0 + 2 * tp)     * (NV * NH) + v * NH;
        float* dB = g_hv + (size_t)(n0 + t0 + 2 * tp + 1) * (NV * NH) + v * NH;
        *(float4*)(dA + cA)       = make_float4(q0.x, q1.x, q2.x, q3.x);
        *(float4*)(dA + cA + 128) = make_float4(q4.x, q5.x, q6.x, q7.x);
        *(float4*)(dB + cA)       = make_float4(q0.y, q1.y, q2.y, q3.y);
        *(float4*)(dB + cA + 128) = make_float4(q4.y, q5.y, q6.y, q7.y);
    }
}

// ---------------------------------------------------------------------------
// Kernel 3: per-token LN(256) per v + weight scale + sum over v -> selected
// ---------------------------------------------------------------------------
__global__ void combine_kernel(const float* __restrict__ lng, const float* __restrict__ lnb,
                               const float* __restrict__ wts, float* __restrict__ out_sel)
{
    __shared__ float s_part[8 * 260];
    const int n = blockIdx.x;
    const int tid = threadIdx.x;
    const int w = tid >> 5, lane = tid & 31;

    float psum[8];
#pragma unroll
    for (int j = 0; j < 8; ++j) psum[j] = 0.f;

#pragma unroll
    for (int vv = 0; vv < 2; ++vv) {
        int v = w * 2 + vv;
        const float* p = g_hv + (size_t)n * (NV * NH) + v * NH + lane * 8;
        float4 u0 = *(const float4*)p, u1 = *(const float4*)(p + 4);
        float uu[8] = {u0.x, u0.y, u0.z, u0.w, u1.x, u1.y, u1.z, u1.w};
        float s = 0.f, s2 = 0.f;
#pragma unroll
        for (int j = 0; j < 8; ++j) { s += uu[j]; s2 += uu[j] * uu[j]; }
#pragma unroll
        for (int off = 16; off > 0; off >>= 1) {
            s  += __shfl_xor_sync(0xffffffffu, s,  off);
            s2 += __shfl_xor_sync(0xffffffffu, s2, off);
        }
        float mu   = s * (1.f / 256.f);
        float var  = s2 * (1.f / 256.f) - mu * mu;
        float rstd = rsqrtf(var + 1e-5f);
        float wv = wts[n * NV + v];
#pragma unroll
        for (int j = 0; j < 8; ++j) {
            int c = lane * 8 + j;
            float y = (uu[j] - mu) * rstd * lng[v * NH + c] + lnb[v * NH + c];
            psum[j] += y * wv;
        }
    }

    *(float4*)(s_part + w * 260 + lane * 8)     = make_float4(psum[0], psum[1], psum[2], psum[3]);
    *(float4*)(s_part + w * 260 + lane * 8 + 4) = make_float4(psum[4], psum[5], psum[6], psum[7]);
    __syncthreads();

    float s = 0.f;
#pragma unroll
    for (int w8 = 0; w8 < 8; ++w8) s += s_part[w8 * 260 + tid];
    out_sel[(size_t)n * NH + tid] = s;
}

// ---------------------------------------------------------------------------
extern "C" void kernel_launch(void* const* d_in, const int* in_sizes, int n_in,
                              void* d_out, int out_size)
{
    const float* x        = (const float*)d_in[0];
    const float* context  = (const float*)d_in[1];
    const float* vg_fc1_w = (const float*)d_in[2];
    const float* vg_fc1_b = (const float*)d_in[3];
    const float* vg_fc2_w = (const float*)d_in[4];
    const float* vg_fc2_b = (const float*)d_in[5];
    const float* vg_glu_w = (const float*)d_in[6];
    const float* vg_glu_b = (const float*)d_in[7];
    const float* vg_skip_w= (const float*)d_in[8];
    const float* vg_skip_b= (const float*)d_in[9];
    const float* vg_ln_g  = (const float*)d_in[10];
    const float* vg_ln_b  = (const float*)d_in[11];
    const float* wg_fc1_w = (const float*)d_in[12];
    const float* wg_fc1_b = (const float*)d_in[13];
    const float* wg_ctx_w = (const float*)d_in[14];
    const float* wg_fc2_w = (const float*)d_in[15];
    const float* wg_fc2_b = (const float*)d_in[16];
    const float* wg_glu_w = (const float*)d_in[17];
    const float* wg_glu_b = (const float*)d_in[18];
    const float* wg_skip_w= (const float*)d_in[19];
    const float* wg_skip_b= (const float*)d_in[20];
    const float* wg_ln_g  = (const float*)d_in[21];
    const float* wg_ln_b  = (const float*)d_in[22];

    float* out      = (float*)d_out;
    float* out_sel  = out;
    float* out_wts  = out + (size_t)NTOK * NH;

    const int WG_SMEM = (128 * PAD + 2 * 256 * PAD + 64 * 16 + 64 * 32 + 128 * 16) * 4; // ~187KB
    const int G_SMEM  = NS * BK * (GTOK + NH) * 4;                                      // 80KB/block
    cudaFuncSetAttribute(wg_kernel,      cudaFuncAttributeMaxDynamicSharedMemorySize, WG_SMEM);
    cudaFuncSetAttribute(wgfc1_kernel,   cudaFuncAttributeMaxDynamicSharedMemorySize, G_SMEM);
    cudaFuncSetAttribute(fc1skip_kernel, cudaFuncAttributeMaxDynamicSharedMemorySize, G_SMEM);
    cudaFuncSetAttribute(fc2_kernel,     cudaFuncAttributeMaxDynamicSharedMemorySize, G_SMEM);
    cudaFuncSetAttribute(glu_a_kernel,   cudaFuncAttributeMaxDynamicSharedMemorySize, G_SMEM);
    cudaFuncSetAttribute(glu_b_kernel,   cudaFuncAttributeMaxDynamicSharedMemorySize, G_SMEM);

    const dim3 xgrid(NTOK / GT, NV);
    const dim3 ggrid(NTOK / GTOK, NV);

    ctx_kernel<<<32, NH>>>(context, wg_ctx_w);
    xt_kernel<<<xgrid, 256>>>(x);

    wgfc1_kernel<<<dim3(NTOK / GTOK, 2), 256, G_SMEM>>>(wg_fc1_w);
    wg_kernel<<<NTOK / TT, NTH, WG_SMEM>>>(
        x, wg_fc1_b, wg_fc2_w, wg_fc2_b, wg_glu_w, wg_glu_b,
        wg_skip_w, wg_skip_b, wg_ln_g, wg_ln_b, out_wts);

    fc1skip_kernel<<<ggrid, 256, G_SMEM>>>(vg_fc1_w, vg_fc1_b, vg_skip_w, vg_skip_b);
    fc2_kernel<<<ggrid, 256, G_SMEM>>>(vg_fc2_w, vg_fc2_b);
    glu_a_kernel<<<ggrid, 256, G_SMEM>>>(vg_glu_w, vg_glu_b);
    glu_b_kernel<<<ggrid, 256, G_SMEM>>>(vg_glu_w, vg_glu_b);

    combine_kernel<<<NTOK, 256>>>(vg_ln_g, vg_ln_b, out_wts, out_sel);
}

// round 15
// speedup vs baseline: 1.1432x; 1.0409x over previous
#include <cuda_runtime.h>
#include <math.h>
#include <stdint.h>

// Problem constants
#define NTH   512
#define PAD   65
#define NV    16
#define ND    64
#define NH    256
#define NC    128
#define NTOK  8192
#define TT    64     // wg token tile
#define GT    128    // xt token tile
#define GTOK  64     // gemm token tile
#define BK    16     // gemm k-chunk
#define NS    4      // pipeline stages
#define SP    132    // xt smem pad

typedef unsigned long long u64;

// Scratch (device globals: allocation-free rule)
__device__ float g_ctxp[32 * NH];
__device__ float g_xT[NV * ND * NTOK];        // x transposed [v][d][n] == flat^T [k][n]
__device__ float g_h1[NV * NH * NTOK];        // elu(fc1) [v][c][n]
__device__ float g_res[NV * NH * NTOK];       // skip residual [v][c][n]
__device__ float g_h2[NV * NH * NTOK];        // fc2 out [v][c][n]
__device__ float g_a[NV * NH * NTOK];         // glu a-half [v][c][n]
__device__ float g_hv[NTOK * NV * NH];        // raw hv (pre-LN) [n][v][c]
__device__ float g_wh1[2 * NH * NTOK];        // wg fc1 partials [khalf][c][n]
__device__ float g_wh1f[NH * NTOK];           // wg h1 formed [c][n]
__device__ float g_wh2[NH * NTOK];            // wg fc2 out (+bias) [c][n]
__device__ float g_wres2[2 * NTOK * NV];      // wg residual partials [khalf][n][16]

__device__ __forceinline__ float elu_f(float x)  { return x > 0.f ? x : (__expf(x) - 1.f); }
__device__ __forceinline__ float sigm_f(float x) { return 1.f / (1.f + __expf(-x)); }
__device__ __forceinline__ float idf(float x)    { return x; }

// ---- packed fp32x2 helpers ----
__device__ __forceinline__ u64 pk2(float a, float b) {
    u64 r; asm("mov.b64 %0, {%1, %2};" : "=l"(r) : "f"(a), "f"(b)); return r;
}
__device__ __forceinline__ void fm2(u64& d, u64 a, u64 b) {
    asm("fma.rn.f32x2 %0, %1, %2, %0;" : "+l"(d) : "l"(a), "l"(b));
}
__device__ __forceinline__ float2 up2(u64 v) {
    float2 f; asm("mov.b64 {%0, %1}, %2;" : "=f"(f.x), "=f"(f.y) : "l"(v)); return f;
}

// ---- cp.async helpers ----
__device__ __forceinline__ void cpa16(unsigned int s, const void* g) {
    asm volatile("cp.async.cg.shared.global [%0], [%1], 16;" :: "r"(s), "l"(g));
}
#define CPA_COMMIT() asm volatile("cp.async.commit_group;" ::: "memory")
#define CPA_WAIT(n)  asm volatile("cp.async.wait_group %0;" :: "n"(n) : "memory")

// ===========================================================================
// Tiled GEMM core: block = 64 tokens x 256 cols, 256 threads, 2 blocks/SM.
// Thread tile: 8 tokens x 8 cols as two split quads (cA..cA+3, cA+128..cA+131).
// ===========================================================================
#define GDECL \
    extern __shared__ float smem[]; \
    float* xs = smem; \
    float* ws = smem + NS * BK * GTOK; \
    const unsigned int xs_u = (unsigned int)__cvta_generic_to_shared(xs); \
    const unsigned int ws_u = (unsigned int)__cvta_generic_to_shared(ws); \
    const int tid = threadIdx.x; \
    const int t0  = (tid >> 5) * 8; \
    const int cA  = (tid & 31) * 4; \
    const int v   = blockIdx.y; \
    const int n0  = blockIdx.x * GTOK; \
    u64 acc[8][4]; \
    (void)v;

#define GCOL(c) (cA + ((c) & 3) + (((c) >> 2) * 128))

#define GZERO() do { \
    _Pragma("unroll") for (int _c = 0; _c < 8; ++_c) \
    _Pragma("unroll") for (int _t = 0; _t < 4; ++_t) acc[_c][_t] = 0ull; \
} while (0)

#define ISSUE(APTR, WPTR, WS_, k0, buf) do { \
    { int kr = tid >> 4, cc = tid & 15; \
      cpa16(xs_u + (((buf) * BK + kr) * GTOK + cc * 4) * 4, \
            (APTR) + (size_t)((k0) + kr) * NTOK + cc * 4); } \
    _Pragma("unroll") \
    for (int s2 = 0; s2 < 4; ++s2) { \
      int ci = tid + s2 * 256; int kr = ci >> 6, cc = ci & 63; \
      cpa16(ws_u + (((buf) * BK + kr) * NH + cc * 4) * 4, \
            (WPTR) + (size_t)((k0) + kr) * (WS_) + cc * 4); } \
} while (0)

#define GFMA8() do { \
    u64 xp0 = pk2(xa.x, xa.y), xp1 = pk2(xa.z, xa.w); \
    u64 xp2 = pk2(xb.x, xb.y), xp3 = pk2(xb.z, xb.w); \
    u64 q; \
    q = pk2(wa.x, wa.x); fm2(acc[0][0], q, xp0); fm2(acc[0][1], q, xp1); fm2(acc[0][2], q, xp2); fm2(acc[0][3], q, xp3); \
    q = pk2(wa.y, wa.y); fm2(acc[1][0], q, xp0); fm2(acc[1][1], q, xp1); fm2(acc[1][2], q, xp2); fm2(acc[1][3], q, xp3); \
    q = pk2(wa.z, wa.z); fm2(acc[2][0], q, xp0); fm2(acc[2][1], q, xp1); fm2(acc[2][2], q, xp2); fm2(acc[2][3], q, xp3); \
    q = pk2(wa.w, wa.w); fm2(acc[3][0], q, xp0); fm2(acc[3][1], q, xp1); fm2(acc[3][2], q, xp2); fm2(acc[3][3], q, xp3); \
    q = pk2(wb.x, wb.x); fm2(acc[4][0], q, xp0); fm2(acc[4][1], q, xp1); fm2(acc[4][2], q, xp2); fm2(acc[4][3], q, xp3); \
    q = pk2(wb.y, wb.y); fm2(acc[5][0], q, xp0); fm2(acc[5][1], q, xp1); fm2(acc[5][2], q, xp2); fm2(acc[5][3], q, xp3); \
    q = pk2(wb.z, wb.z); fm2(acc[6][0], q, xp0); fm2(acc[6][1], q, xp1); fm2(acc[6][2], q, xp2); fm2(acc[6][3], q, xp3); \
    q = pk2(wb.w, wb.w); fm2(acc[7][0], q, xp0); fm2(acc[7][1], q, xp1); fm2(acc[7][2], q, xp2); fm2(acc[7][3], q, xp3); \
} while (0)

#define GCHUNK(buf) do { \
    const float* xr = xs + (buf) * BK * GTOK + t0; \
    const float* wr = ws + (buf) * BK * NH + cA; \
    _Pragma("unroll") \
    for (int kk = 0; kk < BK; ++kk) { \
        float4 xa = *(const float4*)(xr + kk * GTOK); \
        float4 xb = *(const float4*)(xr + kk * GTOK + 4); \
        float4 wa = *(const float4*)(wr + kk * NH); \
        float4 wb = *(const float4*)(wr + kk * NH + 128); \
        GFMA8(); \
    } \
} while (0)

#define GRUN(APTR, WPTR, WS_, KN) do { \
    const int nkc = (KN) / BK; \
    _Pragma("unroll") \
    for (int p = 0; p < NS - 1; ++p) { \
        if (p < nkc) { ISSUE(APTR, WPTR, WS_, p * BK, p); CPA_COMMIT(); } \
    } \
    for (int kc = 0; kc < nkc; ++kc) { \
        CPA_WAIT(NS - 2); \
        __syncthreads(); \
        if (kc + NS - 1 < nkc) { \
            ISSUE(APTR, WPTR, WS_, (kc + NS - 1) * BK, (kc + NS - 1) % NS); \
            CPA_COMMIT(); \
        } \
        GCHUNK(kc % NS); \
    } \
} while (0)

#define GEPI(OUTP, BIASP, OP) do { \
    _Pragma("unroll") \
    for (int c = 0; c < 8; ++c) { \
        int col = GCOL(c); float bb = (BIASP)[col]; \
        float2 p0 = up2(acc[c][0]), p1 = up2(acc[c][1]); \
        float2 p2 = up2(acc[c][2]), p3 = up2(acc[c][3]); \
        float* d = (OUTP) + (size_t)col * NTOK + n0 + t0; \
        *(float4*)d       = make_float4(OP(p0.x + bb), OP(p0.y + bb), OP(p1.x + bb), OP(p1.y + bb)); \
        *(float4*)(d + 4) = make_float4(OP(p2.x + bb), OP(p2.y + bb), OP(p3.x + bb), OP(p3.y + bb)); \
    } \
} while (0)

// ---------------------------------------------------------------------------
// Kernel 0: context projection
// ---------------------------------------------------------------------------
__global__ void ctx_kernel(const float* __restrict__ ctx, const float* __restrict__ wctx)
{
    int b = blockIdx.x;
    int h = threadIdx.x;
    float acc = 0.f;
    for (int c = 0; c < NC; ++c)
        acc += ctx[b * NC + c] * wctx[c * NH + h];
    g_ctxp[b * NH + h] = acc;
}

// ---------------------------------------------------------------------------
// Kernel: transpose x[n][v][d] -> g_xT[v][d][n]
// ---------------------------------------------------------------------------
__global__ void xt_kernel(const float* __restrict__ x)
{
    __shared__ float s[64 * SP];
    const int v  = blockIdx.y;
    const int n0 = blockIdx.x * GT;
    const int tid = threadIdx.x;

#pragma unroll
    for (int r = 0; r < 8; ++r) {
        int idx = tid + r * 256;
        int t  = idx >> 4;
        int dq = idx & 15;
        float4 val = *(const float4*)(x + (size_t)(n0 + t) * 1024 + v * 64 + dq * 4);
        s[(dq * 4 + 0) * SP + t] = val.x;
        s[(dq * 4 + 1) * SP + t] = val.y;
        s[(dq * 4 + 2) * SP + t] = val.z;
        s[(dq * 4 + 3) * SP + t] = val.w;
    }
    __syncthreads();
#pragma unroll
    for (int r = 0; r < 8; ++r) {
        int idx = tid + r * 256;
        int d  = idx >> 5;
        int tq = idx & 31;
        float4 o = *(const float4*)(s + d * SP + tq * 4);
        *(float4*)(g_xT + ((size_t)v * ND + d) * NTOK + n0 + tq * 4) = o;
    }
}

// ---------------------------------------------------------------------------
// Kernel: wg fc1 K-split GEMM + fused skip-residual partials.
// blockIdx.y = K-half (512 each). Raw fc1 partials -> g_wh1[kh][c][n];
// residual partials -> g_wres2[kh][n][16].
// ---------------------------------------------------------------------------
__global__ __launch_bounds__(256, 2)
void wgfc1_kernel(const float* __restrict__ fc1w, const float* __restrict__ skw)
{
    extern __shared__ float smem[];
    float* xs = smem;
    float* ws = smem + NS * BK * GTOK;
    float* sk = ws + NS * BK * NH;
    const unsigned int xs_u = (unsigned int)__cvta_generic_to_shared(xs);
    const unsigned int ws_u = (unsigned int)__cvta_generic_to_shared(ws);
    const unsigned int sk_u = (unsigned int)__cvta_generic_to_shared(sk);
    const int tid  = threadIdx.x;
    const int t0   = (tid >> 5) * 8;
    const int cA   = (tid & 31) * 4;
    const int lane = tid & 31;
    const int kh   = blockIdx.y;
    const int n0   = blockIdx.x * GTOK;
    u64 acc[8][4];
    float racc[8];
    GZERO();
#pragma unroll
    for (int i = 0; i < 8; ++i) racc[i] = 0.f;

    const float* A  = g_xT + (size_t)kh * 512 * NTOK + n0;
    const float* W  = fc1w + (size_t)kh * 512 * NH;
    const float* SK = skw  + (size_t)kh * 512 * NV;

#define WISSUE(k0, buf) do { \
    { int kr = tid >> 4, cc = tid & 15; \
      cpa16(xs_u + (((buf) * BK + kr) * GTOK + cc * 4) * 4, A + (size_t)((k0) + kr) * NTOK + cc * 4); } \
    _Pragma("unroll") \
    for (int s2 = 0; s2 < 4; ++s2) { \
      int ci = tid + s2 * 256; int kr = ci >> 6, cc = ci & 63; \
      cpa16(ws_u + (((buf) * BK + kr) * NH + cc * 4) * 4, W + (size_t)((k0) + kr) * NH + cc * 4); } \
    if (tid < 64) { int kr = tid >> 2, cc = tid & 3; \
      cpa16(sk_u + (((buf) * BK + kr) * NV + cc * 4) * 4, SK + (size_t)((k0) + kr) * NV + cc * 4); } \
} while (0)

    const int nkc = 512 / BK;
#pragma unroll
    for (int p = 0; p < NS - 1; ++p) { WISSUE(p * BK, p); CPA_COMMIT(); }
    for (int kc = 0; kc < nkc; ++kc) {
        CPA_WAIT(NS - 2);
        __syncthreads();
        if (kc + NS - 1 < nkc) { WISSUE((kc + NS - 1) * BK, (kc + NS - 1) % NS); CPA_COMMIT(); }
        int buf = kc % NS;
        const float* xr  = xs + buf * BK * GTOK + t0;
        const float* wr  = ws + buf * BK * NH + cA;
        const float* skr = sk + buf * BK * NV;
#pragma unroll
        for (int kk = 0; kk < BK; ++kk) {
            float4 xa = *(const float4*)(xr + kk * GTOK);
            float4 xb = *(const float4*)(xr + kk * GTOK + 4);
            float4 wa = *(const float4*)(wr + kk * NH);
            float4 wb = *(const float4*)(wr + kk * NH + 128);
            if (lane < NV) {
                float wv = skr[kk * NV + lane];
                racc[0] += xa.x * wv; racc[1] += xa.y * wv;
                racc[2] += xa.z * wv; racc[3] += xa.w * wv;
                racc[4] += xb.x * wv; racc[5] += xb.y * wv;
                racc[6] += xb.z * wv; racc[7] += xb.w * wv;
            }
            GFMA8();
        }
    }
#undef WISSUE

#pragma unroll
    for (int c = 0; c < 8; ++c) {
        int col = GCOL(c);
        float2 p0 = up2(acc[c][0]), p1 = up2(acc[c][1]);
        float2 p2 = up2(acc[c][2]), p3 = up2(acc[c][3]);
        float* d = g_wh1 + ((size_t)kh * NH + col) * NTOK + n0 + t0;
        *(float4*)d       = make_float4(p0.x, p0.y, p1.x, p1.y);
        *(float4*)(d + 4) = make_float4(p2.x, p2.y, p3.x, p3.y);
    }
    if (lane < NV) {
#pragma unroll
        for (int i = 0; i < 8; ++i)
            g_wres2[((size_t)kh * NTOK + n0 + t0 + i) * NV + lane] = racc[i];
    }
}

// ---------------------------------------------------------------------------
// Kernel: h1 = elu(p0 + p1 + fc1b + ctx) -> g_wh1f [c][n]
// ---------------------------------------------------------------------------
__global__ void h1form_kernel(const float* __restrict__ fc1b)
{
    int idx = (blockIdx.x * 256 + threadIdx.x) * 4;
    int c = idx >> 13;
    int n = idx & 8191;
    int b = n >> 8;
    float bb = fc1b[c] + g_ctxp[b * NH + c];
    float4 u0 = *(const float4*)(g_wh1 + idx);
    float4 u1 = *(const float4*)(g_wh1 + (size_t)NH * NTOK + idx);
    float4 o = make_float4(elu_f(u0.x + u1.x + bb), elu_f(u0.y + u1.y + bb),
                           elu_f(u0.z + u1.z + bb), elu_f(u0.w + u1.w + bb));
    *(float4*)(g_wh1f + idx) = o;
}

// ---------------------------------------------------------------------------
// Kernel: wg fc2 GEMM: g_wh2 = g_wh1f @ fc2w + fc2b   (K = 256)
// ---------------------------------------------------------------------------
__global__ __launch_bounds__(256, 2)
void wgfc2_kernel(const float* __restrict__ fc2w, const float* __restrict__ fc2b)
{
    GDECL;
    const float* A = g_wh1f + n0;

    GZERO();
    GRUN(A, fc2w, NH, NH);
    GEPI(g_wh2, fc2b, idf);
}

// ---------------------------------------------------------------------------
// Kernel 1: wg final: glu + GLU + residual + LN(16) + softmax(16)
// ---------------------------------------------------------------------------
__global__ __launch_bounds__(NTH, 1)
void wg_kernel(const float* __restrict__ gluw, const float* __restrict__ glub,
               const float* __restrict__ skb,
               const float* __restrict__ lng,  const float* __restrict__ lnb,
               float* __restrict__ outw)
{
    extern __shared__ float sm[];
    float* bsh = sm;                       // [256][PAD]  h2 (incl bias)
    float* rsh = bsh + 256 * PAD;          // [64][16]    residual
    float* gsh = rsh + 64 * 16;            // [64][32]    glu pre-act

    const int tid  = threadIdx.x;
    const int warp = tid >> 5, lane = tid & 31;
    const int t0 = warp * 4;
    const int n0 = blockIdx.x * TT;

    // ---- load h2 -> bsh, residual -> rsh ----
    for (int i = tid; i < 256 * 16; i += NTH) {
        int c = i >> 4, tq = i & 15;
        float4 u = *(const float4*)(g_wh2 + (size_t)c * NTOK + n0 + tq * 4);
        bsh[c * PAD + tq * 4 + 0] = u.x;
        bsh[c * PAD + tq * 4 + 1] = u.y;
        bsh[c * PAD + tq * 4 + 2] = u.z;
        bsh[c * PAD + tq * 4 + 3] = u.w;
    }
    if (tid < 256) {
        float4 u0 = *(const float4*)(g_wres2 + (size_t)n0 * NV + tid * 4);
        float4 u1 = *(const float4*)(g_wres2 + (size_t)NTOK * NV + (size_t)n0 * NV + tid * 4);
        int p = tid * 4;
        rsh[p + 0] = u0.x + u1.x + skb[(p + 0) & 15];
        rsh[p + 1] = u0.y + u1.y + skb[(p + 1) & 15];
        rsh[p + 2] = u0.z + u1.z + skb[(p + 2) & 15];
        rsh[p + 3] = u0.w + u1.w + skb[(p + 3) & 15];
    }
    __syncthreads();

    // ---- glu: g = h2 @ glu_w + glu_b (K=256, 32 cols) ----
    {
        float a3[4] = {0.f, 0.f, 0.f, 0.f};
#pragma unroll 4
        for (int k = 0; k < NH; ++k) {
            float w = gluw[k * 32 + lane];
            a3[0] += bsh[k * PAD + t0 + 0] * w;
            a3[1] += bsh[k * PAD + t0 + 1] * w;
            a3[2] += bsh[k * PAD + t0 + 2] * w;
            a3[3] += bsh[k * PAD + t0 + 3] * w;
        }
        float gb = glub[lane];
#pragma unroll
        for (int i = 0; i < 4; ++i)
            gsh[(t0 + i) * 32 + lane] = a3[i] + gb;
    }
    __syncthreads();

    // ---- GLU + residual + LN(16) + softmax(16) ----
    if (tid < TT) {
        int t = tid;
        float h[NV];
        float mu = 0.f;
#pragma unroll
        for (int v = 0; v < NV; ++v) {
            float a  = gsh[t * 32 + v];
            float bb = gsh[t * 32 + 16 + v];
            h[v] = a * sigm_f(bb) + rsh[t * 16 + v];
            mu += h[v];
        }
        mu *= (1.f / 16.f);
        float var = 0.f;
#pragma unroll
        for (int v = 0; v < NV; ++v) { float d = h[v] - mu; var += d * d; }
        var *= (1.f / 16.f);
        float rstd = rsqrtf(var + 1e-5f);
        float y[NV], m = -1e30f;
#pragma unroll
        for (int v = 0; v < NV; ++v) {
            y[v] = (h[v] - mu) * rstd * lng[v] + lnb[v];
            m = fmaxf(m, y[v]);
        }
        float s = 0.f;
#pragma unroll
        for (int v = 0; v < NV; ++v) { y[v] = __expf(y[v] - m); s += y[v]; }
        float inv = 1.f / s;
#pragma unroll
        for (int v = 0; v < NV; ++v)
            outw[(n0 + t) * NV + v] = y[v] * inv;
    }
}

// ---------------------------------------------------------------------------
// Kernel 2a: h1 = elu(x @ fc1 + b1), res = x @ skip + bs   (K = 64)
// ---------------------------------------------------------------------------
__global__ __launch_bounds__(256, 2)
void fc1skip_kernel(const float* __restrict__ fc1w, const float* __restrict__ fc1b,
                    const float* __restrict__ skw,  const float* __restrict__ skb)
{
    GDECL;
    const float* A  = g_xT + (size_t)v * ND * NTOK + n0;
    const float* W1 = fc1w + (size_t)v * ND * NH;
    const float* W2 = skw  + (size_t)v * ND * NH;

    GZERO();
    GRUN(A, W1, NH, ND);
    GEPI(g_h1 + (size_t)v * NH * NTOK, fc1b + v * NH, elu_f);

    GZERO();
    GRUN(A, W2, NH, ND);
    GEPI(g_res + (size_t)v * NH * NTOK, skb + v * NH, idf);
}

// ---------------------------------------------------------------------------
// Kernel 2b: h2 = h1 @ fc2 + b2   (K = 256)
// ---------------------------------------------------------------------------
__global__ __launch_bounds__(256, 2)
void fc2_kernel(const float* __restrict__ fc2w, const float* __restrict__ fc2b)
{
    GDECL;
    const float* A = g_h1 + (size_t)v * NH * NTOK + n0;
    const float* W = fc2w + (size_t)v * NH * NH;

    GZERO();
    GRUN(A, W, NH, NH);
    GEPI(g_h2 + (size_t)v * NH * NTOK, fc2b + v * NH, idf);
}

// ---------------------------------------------------------------------------
// Kernel 2c-1: a-half of GLU -> g_a   (K = 256)
// ---------------------------------------------------------------------------
__global__ __launch_bounds__(256, 2)
void glu_a_kernel(const float* __restrict__ gluw, const float* __restrict__ glub)
{
    GDECL;
    const float* A = g_h2 + (size_t)v * NH * NTOK + n0;
    const float* W = gluw + (size_t)v * NH * 512;

    GZERO();
    GRUN(A, W, 512, NH);
    GEPI(g_a + (size_t)v * NH * NTOK, glub + v * 512, idf);
}

// ---------------------------------------------------------------------------
// Kernel 2c-2: b-half + combine: hv = a * sigm(b) + res -> g_hv [n][v][c]
// ---------------------------------------------------------------------------
__global__ __launch_bounds__(256, 2)
void glu_b_kernel(const float* __restrict__ gluw, const float* __restrict__ glub)
{
    GDECL;
    const float* A = g_h2 + (size_t)v * NH * NTOK + n0;
    const float* W = gluw + (size_t)v * NH * 512 + 256;

    GZERO();
    GRUN(A, W, 512, NH);

#pragma unroll
    for (int c = 0; c < 8; ++c) {
        int col = GCOL(c);
        float bb = glub[v * 512 + 256 + col];
        const float* ap = g_a   + ((size_t)v * NH + col) * NTOK + n0 + t0;
        const float* rp = g_res + ((size_t)v * NH + col) * NTOK + n0 + t0;
        float4 a0 = *(const float4*)ap, a1 = *(const float4*)(ap + 4);
        float4 r0 = *(const float4*)rp, r1 = *(const float4*)(rp + 4);
        float2 p0 = up2(acc[c][0]), p1 = up2(acc[c][1]);
        float2 p2 = up2(acc[c][2]), p3 = up2(acc[c][3]);
        float h0 = a0.x * sigm_f(p0.x + bb) + r0.x;
        float h1 = a0.y * sigm_f(p0.y + bb) + r0.y;
        float h2 = a0.z * sigm_f(p1.x + bb) + r0.z;
        float h3 = a0.w * sigm_f(p1.y + bb) + r0.w;
        float h4 = a1.x * sigm_f(p2.x + bb) + r1.x;
        float h5 = a1.y * sigm_f(p2.y + bb) + r1.y;
        float h6 = a1.z * sigm_f(p3.x + bb) + r1.z;
        float h7 = a1.w * sigm_f(p3.y + bb) + r1.w;
        acc[c][0] = pk2(h0, h1); acc[c][1] = pk2(h2, h3);
        acc[c][2] = pk2(h4, h5); acc[c][3] = pk2(h6, h7);
    }

#pragma unroll
    for (int tp = 0; tp < 4; ++tp) {
        float2 q0 = up2(acc[0][tp]), q1 = up2(acc[1][tp]);
        float2 q2 = up2(acc[2][tp]), q3 = up2(acc[3][tp]);
        float2 q4 = up2(acc[4][tp]), q5 = up2(acc[5][tp]);
        float2 q6 = up2(acc[6][tp]), q7 = up2(acc[7][tp]);
        float* dA = g_hv + (size_t)(n0 + t0 + 2 * tp)     * (NV * NH) + v * NH;
        float* dB = g_hv + (size_t)(n0 + t0 + 2 * tp + 1) * (NV * NH) + v * NH;
        *(float4*)(dA + cA)       = make_float4(q0.x, q1.x, q2.x, q3.x);
        *(float4*)(dA + cA + 128) = make_float4(q4.x, q5.x, q6.x, q7.x);
        *(float4*)(dB + cA)       = make_float4(q0.y, q1.y, q2.y, q3.y);
        *(float4*)(dB + cA + 128) = make_float4(q4.y, q5.y, q6.y, q7.y);
    }
}

// ---------------------------------------------------------------------------
// Kernel 3: per-token LN(256) per v + weight scale + sum over v -> selected
// ---------------------------------------------------------------------------
__global__ void combine_kernel(const float* __restrict__ lng, const float* __restrict__ lnb,
                               const float* __restrict__ wts, float* __restrict__ out_sel)
{
    __shared__ float s_part[8 * 260];
    const int n = blockIdx.x;
    const int tid = threadIdx.x;
    const int w = tid >> 5, lane = tid & 31;

    float psum[8];
#pragma unroll
    for (int j = 0; j < 8; ++j) psum[j] = 0.f;

#pragma unroll
    for (int vv = 0; vv < 2; ++vv) {
        int v = w * 2 + vv;
        const float* p = g_hv + (size_t)n * (NV * NH) + v * NH + lane * 8;
        float4 u0 = *(const float4*)p, u1 = *(const float4*)(p + 4);
        float uu[8] = {u0.x, u0.y, u0.z, u0.w, u1.x, u1.y, u1.z, u1.w};
        float s = 0.f, s2 = 0.f;
#pragma unroll
        for (int j = 0; j < 8; ++j) { s += uu[j]; s2 += uu[j] * uu[j]; }
#pragma unroll
        for (int off = 16; off > 0; off >>= 1) {
            s  += __shfl_xor_sync(0xffffffffu, s,  off);
            s2 += __shfl_xor_sync(0xffffffffu, s2, off);
        }
        float mu   = s * (1.f / 256.f);
        float var  = s2 * (1.f / 256.f) - mu * mu;
        float rstd = rsqrtf(var + 1e-5f);
        float wv = wts[n * NV + v];
#pragma unroll
        for (int j = 0; j < 8; ++j) {
            int c = lane * 8 + j;
            float y = (uu[j] - mu) * rstd * lng[v * NH + c] + lnb[v * NH + c];
            psum[j] += y * wv;
        }
    }

    *(float4*)(s_part + w * 260 + lane * 8)     = make_float4(psum[0], psum[1], psum[2], psum[3]);
    *(float4*)(s_part + w * 260 + lane * 8 + 4) = make_float4(psum[4], psum[5], psum[6], psum[7]);
    __syncthreads();

    float s = 0.f;
#pragma unroll
    for (int w8 = 0; w8 < 8; ++w8) s += s_part[w8 * 260 + tid];
    out_sel[(size_t)n * NH + tid] = s;
}

// ---------------------------------------------------------------------------
extern "C" void kernel_launch(void* const* d_in, const int* in_sizes, int n_in,
                              void* d_out, int out_size)
{
    const float* x        = (const float*)d_in[0];
    const float* context  = (const float*)d_in[1];
    const float* vg_fc1_w = (const float*)d_in[2];
    const float* vg_fc1_b = (const float*)d_in[3];
    const float* vg_fc2_w = (const float*)d_in[4];
    const float* vg_fc2_b = (const float*)d_in[5];
    const float* vg_glu_w = (const float*)d_in[6];
    const float* vg_glu_b = (const float*)d_in[7];
    const float* vg_skip_w= (const float*)d_in[8];
    const float* vg_skip_b= (const float*)d_in[9];
    const float* vg_ln_g  = (const float*)d_in[10];
    const float* vg_ln_b  = (const float*)d_in[11];
    const float* wg_fc1_w = (const float*)d_in[12];
    const float* wg_fc1_b = (const float*)d_in[13];
    const float* wg_ctx_w = (const float*)d_in[14];
    const float* wg_fc2_w = (const float*)d_in[15];
    const float* wg_fc2_b = (const float*)d_in[16];
    const float* wg_glu_w = (const float*)d_in[17];
    const float* wg_glu_b = (const float*)d_in[18];
    const float* wg_skip_w= (const float*)d_in[19];
    const float* wg_skip_b= (const float*)d_in[20];
    const float* wg_ln_g  = (const float*)d_in[21];
    const float* wg_ln_b  = (const float*)d_in[22];

    float* out      = (float*)d_out;
    float* out_sel  = out;
    float* out_wts  = out + (size_t)NTOK * NH;

    const int WG_SMEM  = (256 * PAD + 64 * 16 + 64 * 32) * 4;           // ~79KB
    const int G_SMEM   = NS * BK * (GTOK + NH) * 4;                     // 80KB/block
    const int WF1_SMEM = NS * BK * (GTOK + NH + NV) * 4;                // 84KB/block
    cudaFuncSetAttribute(wg_kernel,      cudaFuncAttributeMaxDynamicSharedMemorySize, WG_SMEM);
    cudaFuncSetAttribute(wgfc1_kernel,   cudaFuncAttributeMaxDynamicSharedMemorySize, WF1_SMEM);
    cudaFuncSetAttribute(wgfc2_kernel,   cudaFuncAttributeMaxDynamicSharedMemorySize, G_SMEM);
    cudaFuncSetAttribute(fc1skip_kernel, cudaFuncAttributeMaxDynamicSharedMemorySize, G_SMEM);
    cudaFuncSetAttribute(fc2_kernel,     cudaFuncAttributeMaxDynamicSharedMemorySize, G_SMEM);
    cudaFuncSetAttribute(glu_a_kernel,   cudaFuncAttributeMaxDynamicSharedMemorySize, G_SMEM);
    cudaFuncSetAttribute(glu_b_kernel,   cudaFuncAttributeMaxDynamicSharedMemorySize, G_SMEM);

    const dim3 xgrid(NTOK / GT, NV);
    const dim3 ggrid(NTOK / GTOK, NV);

    ctx_kernel<<<32, NH>>>(context, wg_ctx_w);
    xt_kernel<<<xgrid, 256>>>(x);

    wgfc1_kernel<<<dim3(NTOK / GTOK, 2), 256, WF1_SMEM>>>(wg_fc1_w, wg_skip_w);
    h1form_kernel<<<2048, 256>>>(wg_fc1_b);
    wgfc2_kernel<<<dim3(NTOK / GTOK, 1), 256, G_SMEM>>>(wg_fc2_w, wg_fc2_b);
    wg_kernel<<<NTOK / TT, NTH, WG_SMEM>>>(
        wg_glu_w, wg_glu_b, wg_skip_b, wg_ln_g, wg_ln_b, out_wts);

    fc1skip_kernel<<<ggrid, 256, G_SMEM>>>(vg_fc1_w, vg_fc1_b, vg_skip_w, vg_skip_b);
    fc2_kernel<<<ggrid, 256, G_SMEM>>>(vg_fc2_w, vg_fc2_b);
    glu_a_kernel<<<ggrid, 256, G_SMEM>>>(vg_glu_w, vg_glu_b);
    glu_b_kernel<<<ggrid, 256, G_SMEM>>>(vg_glu_w, vg_glu_b);

    combine_kernel<<<NTOK, 256>>>(vg_ln_g, vg_ln_b, out_wts, out_sel);
}